// round 17
// baseline (speedup 1.0000x reference)
#include <cuda_runtime.h>
#include <cuda_fp16.h>
#include <cstdint>

// Problem constants
#define BB 2
#define SS 2048
#define DD 1024
#define HH 16
#define HSZ 64
#define BS (BB * SS)        // 4096 rows
#define D3 (3 * DD)         // 3072
#define DFF (4 * DD)        // 4096

// softmax scale folded with log2e, applied to q in the QKV GEMM epilogue
#define QSCALE 0.1803368801111721f   // 0.125 * log2(e)

// ---------------- scratch (static device memory; no allocations) ----------------
__device__ __half g_xn[BS * DD];
__device__ __half g_qkv[BS * D3];
__device__ __half g_attn[BS * DD];
__device__ float  g_h[BS * DD];
__device__ __half g_hn[BS * DD];
__device__ __half g_ff[BS * DFF];
__device__ __half g_wqkvT[D3 * DD];
__device__ __half g_wprojT[DD * DD];
__device__ __half g_w1T[DFF * DD];
__device__ __half g_w2T[DD * DFF];

// pack two fp32 into one f16x2 register (rn rounding)
__device__ __forceinline__ unsigned pack_h2(float lo, float hi) {
    unsigned r;
    asm("cvt.rn.f16x2.f32 %0, %1, %2;" : "=r"(r) : "f"(hi), "f"(lo));
    return r;
}

// bare exp2 (single MUFU.EX2)
__device__ __forceinline__ float ex2(float x) {
    float r;
    asm("ex2.approx.f32 %0, %1;" : "=f"(r) : "f"(x));
    return r;
}

// ---------------- LayerNorm body (single-pass, 2 barriers) ----------------
__device__ __forceinline__ void ln_body(const float* __restrict__ in,
                                        const float* __restrict__ gamma,
                                        const float* __restrict__ beta,
                                        __half* __restrict__ out, int row, int tid) {
    int lane = tid & 31, wid = tid >> 5;
    float4 xv = ((const float4*)(in + (size_t)row * DD))[tid];

    float s = xv.x + xv.y + xv.z + xv.w;
    float s2 = xv.x * xv.x + xv.y * xv.y + xv.z * xv.z + xv.w * xv.w;
    #pragma unroll
    for (int o = 16; o; o >>= 1) {
        s += __shfl_xor_sync(0xffffffffu, s, o);
        s2 += __shfl_xor_sync(0xffffffffu, s2, o);
    }

    __shared__ float red[16];
    __shared__ float stat[2];
    if (lane == 0) { red[wid] = s; red[8 + wid] = s2; }
    __syncthreads();
    if (tid < 32) {
        float a = (lane < 8) ? red[lane] : 0.0f;
        float b = (lane < 8) ? red[8 + lane] : 0.0f;
        #pragma unroll
        for (int o = 4; o; o >>= 1) {
            a += __shfl_xor_sync(0xffffffffu, a, o);
            b += __shfl_xor_sync(0xffffffffu, b, o);
        }
        if (lane == 0) {
            float mu = a * (1.0f / DD);
            float var = b * (1.0f / DD) - mu * mu;
            stat[0] = mu;
            stat[1] = rsqrtf(var + 1e-5f);
        }
    }
    __syncthreads();
    float mu = stat[0], rstd = stat[1];

    float4 gv = ((const float4*)gamma)[tid];
    float4 bv = ((const float4*)beta)[tid];
    __half2 h0 = __floats2half2_rn((xv.x - mu) * rstd * gv.x + bv.x,
                                   (xv.y - mu) * rstd * gv.y + bv.y);
    __half2 h1 = __floats2half2_rn((xv.z - mu) * rstd * gv.z + bv.z,
                                   (xv.w - mu) * rstd * gv.w + bv.w);
    ((__half2*)(out + (size_t)row * DD))[tid * 2] = h0;
    ((__half2*)(out + (size_t)row * DD))[tid * 2 + 1] = h1;
}

__global__ void ln_kernel(const float* __restrict__ in, const float* __restrict__ gamma,
                          const float* __restrict__ beta, __half* __restrict__ out) {
    ln_body(in, gamma, beta, out, blockIdx.x, threadIdx.x);
}

// ---------------- prep_gate: wqkvT build + LN1 (gates the QKV GEMM) ------------
// blocks [0,768): wqkvT; [768, 768+BS): LN1 rows
__global__ void prep_gate_kernel(
    const float* __restrict__ wq, const float* __restrict__ wk,
    const float* __restrict__ wv, __half* __restrict__ wqkvT,
    const float* __restrict__ x, const float* __restrict__ ln1_g,
    const float* __restrict__ ln1_b, __half* __restrict__ xn) {
    int id = blockIdx.x;
    int tid = threadIdx.x;

    if (id >= 768) {
        ln_body(x, ln1_g, ln1_b, xn, id - 768, tid);
        return;
    }

    __shared__ float sm[64][65];
    int dblk = id & 15;
    int h = (id >> 4) & 15;
    int part = id >> 8;
    const float* w = (part == 0) ? wq : (part == 1) ? wk : wv;
    int d0 = dblk * 64;

    int kk = tid & 63;
    int g4 = tid >> 6;
    #pragma unroll
    for (int i = 0; i < 16; i++) {
        int dl = g4 + i * 4;
        sm[dl][kk] = w[((size_t)(h * DD + d0 + dl)) * HSZ + kk];
    }
    __syncthreads();
    int dc = tid & 63;
    #pragma unroll
    for (int i = 0; i < 16; i++) {
        int kk2 = g4 + i * 4;
        wqkvT[(size_t)(part * DD + h * HSZ + kk2) * DD + d0 + dc] =
            __float2half_rn(sm[dc][kk2]);
    }
}

// ---------------- prep_aux: wproj/w1/w2 transposes (needed from proj onward) ---
// blocks [0,1024): wproj; [1024,5120): w1; [5120,9216): w2
__global__ void prep_aux_kernel(
    const float* __restrict__ wproj, __half* __restrict__ wprojT,
    const float* __restrict__ w1, __half* __restrict__ w1T,
    const float* __restrict__ w2, __half* __restrict__ w2T) {
    int id = blockIdx.x;
    int tid = threadIdx.x;

    __shared__ float t[32][33];
    int tx = tid & 31, ty = tid >> 5;
    const float* in;
    __half* out;
    int bx, by, R, C;
    if (id < 1024) {
        in = wproj; out = wprojT; R = DD; C = DD;
        bx = id & 31; by = id >> 5;
    } else if (id < 5120) {
        int tgt = id - 1024;
        in = w1; out = w1T; R = DD; C = DFF;
        bx = tgt & 127; by = tgt >> 7;
    } else {
        int tgt = id - 5120;
        in = w2; out = w2T; R = DFF; C = DD;
        bx = tgt & 31; by = tgt >> 5;
    }

    int x2 = bx * 32 + tx;
    int y2 = by * 32 + ty;
    #pragma unroll
    for (int i = 0; i < 32; i += 8)
        t[ty + i][tx] = in[(size_t)(y2 + i) * C + x2];
    __syncthreads();
    x2 = by * 32 + tx;
    y2 = bx * 32 + ty;
    #pragma unroll
    for (int i = 0; i < 32; i += 8)
        out[(size_t)(y2 + i) * R + x2] = __float2half_rn(t[tx][ty + i]);
}

// ---------------- tensor-core helpers -------------------------------
__device__ __forceinline__ void ldsm_x4(unsigned& r0, unsigned& r1, unsigned& r2, unsigned& r3,
                                        unsigned addr) {
    asm volatile("ldmatrix.sync.aligned.m8n8.x4.shared.b16 {%0,%1,%2,%3}, [%4];"
                 : "=r"(r0), "=r"(r1), "=r"(r2), "=r"(r3) : "r"(addr));
}

__device__ __forceinline__ void mma_f16(float c[4], unsigned a0, unsigned a1, unsigned a2,
                                        unsigned a3, unsigned b0, unsigned b1) {
    asm volatile(
        "mma.sync.aligned.m16n8k16.row.col.f32.f16.f16.f32 "
        "{%0,%1,%2,%3}, {%4,%5,%6,%7}, {%8,%9}, {%0,%1,%2,%3};"
        : "+f"(c[0]), "+f"(c[1]), "+f"(c[2]), "+f"(c[3])
        : "r"(a0), "r"(a1), "r"(a2), "r"(a3), "r"(b0), "r"(b1));
}

#define CPA16(dst, src) \
    asm volatile("cp.async.cg.shared.global [%0], [%1], 16;" :: "r"(dst), "l"(src))

// ---------------- fp16 GEMM: 128x128 tile, BK=64 halves, 256 thr, 3-stage ------
#define GEMM_SMEM (3 * 32768)

// MODE: 0 = fp32 out (+res), 1 = fp16 out + relu,
//       2 = fp16 out with QSCALE applied to cols < DD (QKV gemm: scales q)
template <int MODE>
__global__ __launch_bounds__(256, 2)
void gemm_tc(const __half* __restrict__ A, const __half* __restrict__ Bt,
             const float* __restrict__ bias, const float* __restrict__ res,
             void* __restrict__ Cv, int M, int N, int K) {
    extern __shared__ unsigned smem_u[];
    unsigned sbase = (unsigned)__cvta_generic_to_shared(smem_u);

    int tid = threadIdx.x;
    int l = tid & 31;
    int wid = tid >> 5;
    int warp_m = wid >> 2;
    int warp_n = wid & 3;
    int bx = blockIdx.x * 128;
    int by = blockIdx.y * 128;

    float acc[4][4][4];
    #pragma unroll
    for (int i = 0; i < 4; i++)
        #pragma unroll
        for (int j = 0; j < 4; j++)
            #pragma unroll
            for (int k = 0; k < 4; k++) acc[i][j][k] = 0.0f;

    int lm = tid >> 3;
    int kc = tid & 7;
    unsigned physc = (unsigned)(kc ^ (lm & 7));
    const __half* aptr = A + (size_t)(by + lm) * K + kc * 8;
    const __half* bptr = Bt + (size_t)(bx + lm) * K + kc * 8;

    int NT = K / 64;

    int rowfrag = (l & 7) + ((l >> 3) & 1) * 8;
    int sel = (l >> 4) & 1;
    int l7 = l & 7;
    int rA = warp_m * 64 + rowfrag;
    int rB = warp_n * 32 + rowfrag;

    auto issue = [&](int kt, unsigned soff) {
        unsigned sA = sbase + soff;
        unsigned sB = sA + 16384u;
        const __half* ap = aptr + kt * 64;
        const __half* bp = bptr + kt * 64;
        #pragma unroll
        for (int i = 0; i < 4; i++) {
            unsigned off = ((unsigned)(lm + 32 * i) * 8 + physc) * 16;
            CPA16(sA + off, ap + (size_t)(32 * i) * K);
            CPA16(sB + off, bp + (size_t)(32 * i) * K);
        }
        asm volatile("cp.async.commit_group;");
    };

    issue(0, 0u);
    issue(1, 32768u);

    unsigned stComp = 0u;
    unsigned stIss = 65536u;

    #pragma unroll 1
    for (int kt = 0; kt < NT; kt++) {
        if (kt < NT - 1) {
            asm volatile("cp.async.wait_group 1;" ::: "memory");
        } else {
            asm volatile("cp.async.wait_group 0;" ::: "memory");
        }
        __syncthreads();

        unsigned sA = sbase + stComp;
        unsigned sB = sA + 16384u;
        stComp = (stComp == 65536u) ? 0u : stComp + 32768u;

        unsigned a[4][4], bf[2][4];
        {
            unsigned phys = (unsigned)(sel ^ l7) * 16u;
            unsigned aBase = sA + (unsigned)rA * 128u + phys;
            unsigned bBase = sB + (unsigned)rB * 128u + phys;
            #pragma unroll
            for (int mt = 0; mt < 4; mt++)
                ldsm_x4(a[mt][0], a[mt][1], a[mt][2], a[mt][3], aBase + mt * 2048u);
            #pragma unroll
            for (int np = 0; np < 2; np++)
                ldsm_x4(bf[np][0], bf[np][1], bf[np][2], bf[np][3], bBase + np * 2048u);
        }

        if (kt + 2 < NT) {
            issue(kt + 2, stIss);
            stIss = (stIss == 65536u) ? 0u : stIss + 32768u;
        }

        #pragma unroll
        for (int mt = 0; mt < 4; mt++)
            #pragma unroll
            for (int nt = 0; nt < 4; nt++)
                mma_f16(acc[mt][nt], a[mt][0], a[mt][1], a[mt][2], a[mt][3],
                        bf[nt >> 1][nt & 1], bf[nt >> 1][(nt & 1) + 2]);

        #pragma unroll
        for (int ks = 1; ks < 4; ks++) {
            unsigned phys = (unsigned)((2 * ks + sel) ^ l7) * 16u;
            unsigned aBase = sA + (unsigned)rA * 128u + phys;
            unsigned bBase = sB + (unsigned)rB * 128u + phys;
            #pragma unroll
            for (int mt = 0; mt < 4; mt++)
                ldsm_x4(a[mt][0], a[mt][1], a[mt][2], a[mt][3], aBase + mt * 2048u);
            #pragma unroll
            for (int np = 0; np < 2; np++)
                ldsm_x4(bf[np][0], bf[np][1], bf[np][2], bf[np][3], bBase + np * 2048u);
            #pragma unroll
            for (int mt = 0; mt < 4; mt++)
                #pragma unroll
                for (int nt = 0; nt < 4; nt++)
                    mma_f16(acc[mt][nt], a[mt][0], a[mt][1], a[mt][2], a[mt][3],
                            bf[nt >> 1][nt & 1], bf[nt >> 1][(nt & 1) + 2]);
        }
    }

    int g = l >> 2, tg = l & 3;
    #pragma unroll
    for (int mt = 0; mt < 4; mt++) {
        int r0 = by + warp_m * 64 + mt * 16 + g;
        #pragma unroll
        for (int nt = 0; nt < 4; nt++) {
            int col = bx + warp_n * 32 + nt * 8 + tg * 2;
            float2 v0 = make_float2(acc[mt][nt][0], acc[mt][nt][1]);
            float2 v1 = make_float2(acc[mt][nt][2], acc[mt][nt][3]);
            if (bias != nullptr) {
                float2 bv = *(const float2*)&bias[col];
                v0.x += bv.x; v0.y += bv.y; v1.x += bv.x; v1.y += bv.y;
            }
            if (MODE == 0) {
                if (res != nullptr) {
                    float2 q0 = *(const float2*)&res[(size_t)r0 * N + col];
                    float2 q1 = *(const float2*)&res[(size_t)(r0 + 8) * N + col];
                    v0.x += q0.x; v0.y += q0.y; v1.x += q1.x; v1.y += q1.y;
                }
                float* C = (float*)Cv;
                *(float2*)&C[(size_t)r0 * N + col] = v0;
                *(float2*)&C[(size_t)(r0 + 8) * N + col] = v1;
            } else {
                if (MODE == 1) {
                    v0.x = fmaxf(v0.x, 0.0f); v0.y = fmaxf(v0.y, 0.0f);
                    v1.x = fmaxf(v1.x, 0.0f); v1.y = fmaxf(v1.y, 0.0f);
                }
                if (MODE == 2 && col < DD) {
                    v0.x *= QSCALE; v0.y *= QSCALE;
                    v1.x *= QSCALE; v1.y *= QSCALE;
                }
                __half* C = (__half*)Cv;
                *(__half2*)&C[(size_t)r0 * N + col] = __floats2half2_rn(v0.x, v0.y);
                *(__half2*)&C[(size_t)(r0 + 8) * N + col] = __floats2half2_rn(v1.x, v1.y);
            }
        }
    }
}

// ---------------- fp16 flash attention, register P, K triple-buffered ----------
#define ATT_SMEM 57344

__global__ __launch_bounds__(256, 2)
void attn_tc(const __half* __restrict__ qkv, __half* __restrict__ out) {
    extern __shared__ char smc[];
    unsigned ub = (unsigned)__cvta_generic_to_shared(smc);
    unsigned uQ = ub;

    int tid = threadIdx.x;
    int l = tid & 31, w = tid >> 5;
    int b = blockIdx.y >> 4, h = blockIdx.y & 15;
    int q0 = ((int)gridDim.x - 1 - (int)blockIdx.x) * 128;
    int nk = q0 / 64 + 2;

    const __half* base = qkv + (size_t)b * SS * D3 + h * HSZ;

    int lr = tid >> 3, lc = tid & 7;
    unsigned lphys = (unsigned)(lc ^ (lr & 7)) * 16u;

    #pragma unroll
    for (int p = 0; p < 4; p++) {
        int row = lr + 32 * p;
        CPA16(uQ + (unsigned)row * 128u + lphys, base + (size_t)(q0 + row) * D3 + lc * 8);
    }
    auto issueK = [&](int kt, unsigned koff) {
        unsigned uK = ub + 16384u + koff;
        int k0 = kt * 64;
        #pragma unroll
        for (int p = 0; p < 2; p++) {
            int row = lr + 32 * p;
            CPA16(uK + (unsigned)row * 128u + lphys,
                  base + (size_t)(k0 + row) * D3 + DD + lc * 8);
        }
        asm volatile("cp.async.commit_group;");
    };

    int vs2 = (tid & 31) * 2, vdg = tid >> 5;
    uint4 vr0, vr1;
    auto loadV = [&](int k0) {
        const __half* vp = base + (size_t)(k0 + vs2) * D3 + 2 * DD + vdg * 8;
        vr0 = *(const uint4*)vp;
        vr1 = *(const uint4*)(vp + D3);
    };
    issueK(0, 0u);
    if (nk > 1) issueK(1, 8192u);
    loadV(0);

    float m2[2] = {-1e30f, -1e30f};
    float l2[2] = {0.0f, 0.0f};
    float oacc[8][4];
    #pragma unroll
    for (int i = 0; i < 8; i++)
        #pragma unroll
        for (int j = 0; j < 4; j++) oacc[i][j] = 0.0f;

    int l7 = l & 7;
    int rowfrag = (l & 7) + ((l >> 3) & 1) * 8;
    int sel = (l >> 4) & 1;
    int rA = w * 16 + rowfrag;
    int rloc = w * 16 + (l >> 2);

    unsigned kComp = 0u;
    unsigned kIss = 16384u;

    unsigned aq[4][4];
    asm volatile("cp.async.wait_group 0;" ::: "memory");
    __syncthreads();
    #pragma unroll
    for (int ks = 0; ks < 4; ks++) {
        unsigned phys = (unsigned)((2 * ks + sel) ^ l7) * 16u;
        ldsm_x4(aq[ks][0], aq[ks][1], aq[ks][2], aq[ks][3], uQ + (unsigned)rA * 128u + phys);
    }

    for (int kt = 0; kt < nk; kt++) {
        int k0 = kt * 64;
        unsigned uK  = ub + 16384u + kComp;
        kComp = (kComp == 16384u) ? 0u : kComp + 8192u;
        unsigned uVT = ub + 40960u + (unsigned)(kt & 1) * 8192u;

        {
            const __half* h0 = (const __half*)&vr0;
            const __half* h1 = (const __half*)&vr1;
            unsigned srow = (unsigned)(vs2 >> 3);
            unsigned scol = (unsigned)(vs2 & 7) * 2u;
            unsigned vtb = 40960u + (unsigned)(kt & 1) * 8192u;
            #pragma unroll
            for (int j = 0; j < 8; j++) {
                int d = vdg * 8 + j;
                unsigned phys = (srow ^ (unsigned)(d & 7)) * 16u;
                *(__half2*)(smc + vtb + (unsigned)d * 128u + phys + scol) =
                    __halves2half2(h0[j], h1[j]);
            }
        }
        if (kt < nk - 1) {
            asm volatile("cp.async.wait_group 1;" ::: "memory");
        } else {
            asm volatile("cp.async.wait_group 0;" ::: "memory");
        }
        __syncthreads();

        if (kt + 2 < nk) {
            issueK(kt + 2, kIss);
            kIss = (kIss == 16384u) ? 0u : kIss + 8192u;
        }
        if (kt + 1 < nk) loadV(k0 + 64);

        float sacc[8][4];
        #pragma unroll
        for (int i = 0; i < 8; i++)
            #pragma unroll
            for (int j = 0; j < 4; j++) sacc[i][j] = 0.0f;

        #pragma unroll
        for (int ks = 0; ks < 4; ks++) {
            unsigned phys = (unsigned)((2 * ks + sel) ^ l7) * 16u;
            unsigned bf[4][4];
            #pragma unroll
            for (int np = 0; np < 4; np++)
                ldsm_x4(bf[np][0], bf[np][1], bf[np][2], bf[np][3],
                        uK + (unsigned)(np * 16 + rowfrag) * 128u + phys);
            #pragma unroll
            for (int nt = 0; nt < 8; nt++)
                mma_f16(sacc[nt], aq[ks][0], aq[ks][1], aq[ks][2], aq[ks][3],
                        bf[nt >> 1][nt & 1], bf[nt >> 1][(nt & 1) + 2]);
        }

        if (kt >= nk - 2) {
            #pragma unroll
            for (int nt = 0; nt < 8; nt++)
                #pragma unroll
                for (int e = 0; e < 4; e++) {
                    int r = q0 + rloc + ((e >> 1) << 3);
                    int c = k0 + nt * 8 + 2 * (l & 3) + (e & 1);
                    if (c > r) sacc[nt][e] = -1e30f;
                }
        }

        #pragma unroll
        for (int i = 0; i < 2; i++) {
            float tm = -1e30f;
            #pragma unroll
            for (int nt = 0; nt < 8; nt++)
                tm = fmaxf(tm, fmaxf(sacc[nt][2 * i], sacc[nt][2 * i + 1]));
            tm = fmaxf(tm, __shfl_xor_sync(0xffffffffu, tm, 1));
            tm = fmaxf(tm, __shfl_xor_sync(0xffffffffu, tm, 2));
            float mn = fmaxf(m2[i], tm);
            float alpha = ex2(m2[i] - mn);
            m2[i] = mn;
            float ls = 0.0f;
            #pragma unroll
            for (int nt = 0; nt < 8; nt++) {
                float p0 = ex2(sacc[nt][2 * i] - mn);
                float p1 = ex2(sacc[nt][2 * i + 1] - mn);
                sacc[nt][2 * i] = p0;
                sacc[nt][2 * i + 1] = p1;
                ls += p0 + p1;
            }
            ls += __shfl_xor_sync(0xffffffffu, ls, 1);
            ls += __shfl_xor_sync(0xffffffffu, ls, 2);
            l2[i] = l2[i] * alpha + ls;
            #pragma unroll
            for (int nt = 0; nt < 8; nt++) {
                oacc[nt][2 * i] *= alpha;
                oacc[nt][2 * i + 1] *= alpha;
            }
        }

        unsigned pa[4][4];
        #pragma unroll
        for (int ks = 0; ks < 4; ks++) {
            pa[ks][0] = pack_h2(sacc[2 * ks][0], sacc[2 * ks][1]);
            pa[ks][1] = pack_h2(sacc[2 * ks][2], sacc[2 * ks][3]);
            pa[ks][2] = pack_h2(sacc[2 * ks + 1][0], sacc[2 * ks + 1][1]);
            pa[ks][3] = pack_h2(sacc[2 * ks + 1][2], sacc[2 * ks + 1][3]);
        }

        #pragma unroll
        for (int ks = 0; ks < 4; ks++) {
            unsigned phys = (unsigned)((2 * ks + sel) ^ l7) * 16u;
            unsigned bf[4][4];
            #pragma unroll
            for (int np = 0; np < 4; np++)
                ldsm_x4(bf[np][0], bf[np][1], bf[np][2], bf[np][3],
                        uVT + (unsigned)(np * 16 + rowfrag) * 128u + phys);
            #pragma unroll
            for (int nt = 0; nt < 8; nt++)
                mma_f16(oacc[nt], pa[ks][0], pa[ks][1], pa[ks][2], pa[ks][3],
                        bf[nt >> 1][nt & 1], bf[nt >> 1][(nt & 1) + 2]);
        }
    }

    float inv0 = 1.0f / l2[0];
    float inv1 = 1.0f / l2[1];
    int r = q0 + rloc;
    int dcol = h * HSZ + 2 * (l & 3);
    #pragma unroll
    for (int nt = 0; nt < 8; nt++) {
        *(__half2*)&out[(size_t)(b * SS + r) * DD + dcol + nt * 8] =
            __floats2half2_rn(oacc[nt][0] * inv0, oacc[nt][1] * inv0);
        *(__half2*)&out[(size_t)(b * SS + r + 8) * DD + dcol + nt * 8] =
            __floats2half2_rn(oacc[nt][2] * inv1, oacc[nt][3] * inv1);
    }
}

// ---------------- launch ----------------
extern "C" void kernel_launch(void* const* d_in, const int* in_sizes, int n_in,
                              void* d_out, int out_size) {
    const float* x     = (const float*)d_in[0];
    const float* wq    = (const float*)d_in[1];
    const float* wk    = (const float*)d_in[2];
    const float* wv    = (const float*)d_in[3];
    const float* wproj = (const float*)d_in[4];
    const float* bproj = (const float*)d_in[5];
    const float* w1    = (const float*)d_in[6];
    const float* b1    = (const float*)d_in[7];
    const float* w2    = (const float*)d_in[8];
    const float* b2    = (const float*)d_in[9];
    const float* ln1_g = (const float*)d_in[10];
    const float* ln1_b = (const float*)d_in[11];
    const float* ln2_g = (const float*)d_in[12];
    const float* ln2_b = (const float*)d_in[13];
    float* out = (float*)d_out;

    __half *p_xn, *p_qkv, *p_attn, *p_hn, *p_ff;
    __half *p_wqkvT, *p_wprojT, *p_w1T, *p_w2T;
    float *p_h;
    cudaGetSymbolAddress((void**)&p_xn, g_xn);
    cudaGetSymbolAddress((void**)&p_qkv, g_qkv);
    cudaGetSymbolAddress((void**)&p_attn, g_attn);
    cudaGetSymbolAddress((void**)&p_h, g_h);
    cudaGetSymbolAddress((void**)&p_hn, g_hn);
    cudaGetSymbolAddress((void**)&p_ff, g_ff);
    cudaGetSymbolAddress((void**)&p_wqkvT, g_wqkvT);
    cudaGetSymbolAddress((void**)&p_wprojT, g_wprojT);
    cudaGetSymbolAddress((void**)&p_w1T, g_w1T);
    cudaGetSymbolAddress((void**)&p_w2T, g_w2T);

    cudaFuncSetAttribute(gemm_tc<0>, cudaFuncAttributeMaxDynamicSharedMemorySize, GEMM_SMEM);
    cudaFuncSetAttribute(gemm_tc<1>, cudaFuncAttributeMaxDynamicSharedMemorySize, GEMM_SMEM);
    cudaFuncSetAttribute(gemm_tc<2>, cudaFuncAttributeMaxDynamicSharedMemorySize, GEMM_SMEM);
    cudaFuncSetAttribute(attn_tc, cudaFuncAttributeMaxDynamicSharedMemorySize, ATT_SMEM);

    // side stream + events for overlapping the aux weight transposes with the
    // QKV GEMM + attention (host-side objects only; leaked deliberately — the
    // few non-replay calls make this negligible, and no device memory moves).
    cudaStream_t s2;
    cudaStreamCreateWithFlags(&s2, cudaStreamNonBlocking);
    cudaEvent_t eFork, eJoin;
    cudaEventCreateWithFlags(&eFork, cudaEventDisableTiming);
    cudaEventCreateWithFlags(&eJoin, cudaEventDisableTiming);

    // fork: aux transposes run concurrently with gate-prep/QKV/attention
    cudaEventRecord(eFork, 0);
    cudaStreamWaitEvent(s2, eFork, 0);
    prep_aux_kernel<<<9216, 256, 0, s2>>>(wproj, p_wprojT, w1, p_w1T, w2, p_w2T);
    cudaEventRecord(eJoin, s2);

    // gate prep: wqkvT + LN1 (only true QKV dependencies)
    prep_gate_kernel<<<768 + BS, 256>>>(wq, wk, wv, p_wqkvT, x, ln1_g, ln1_b, p_xn);

    // QKV GEMM -> fp16 qkv (q pre-scaled by QSCALE)
    gemm_tc<2><<<dim3(D3 / 128, BS / 128), 256, GEMM_SMEM>>>(
        p_xn, p_wqkvT, nullptr, nullptr, p_qkv, BS, D3, DD);

    // fp16 flash attention
    attn_tc<<<dim3(SS / 128, BB * HH), 256, ATT_SMEM>>>(p_qkv, p_attn);

    // join: transposed weights must be ready from here on
    cudaStreamWaitEvent(0, eJoin, 0);

    // proj + bias + residual(x) -> h (fp32)
    gemm_tc<0><<<dim3(DD / 128, BS / 128), 256, GEMM_SMEM>>>(
        p_attn, p_wprojT, bproj, x, p_h, BS, DD, DD);

    // LN2 -> fp16 hn
    ln_kernel<<<BS, 256>>>(p_h, ln2_g, ln2_b, p_hn);

    // FF1 + bias + relu -> fp16 ff
    gemm_tc<1><<<dim3(DFF / 128, BS / 128), 256, GEMM_SMEM>>>(
        p_hn, p_w1T, b1, nullptr, p_ff, BS, DFF, DD);

    // FF2 + bias + residual(h) -> out (fp32)
    gemm_tc<0><<<dim3(DD / 128, BS / 128), 256, GEMM_SMEM>>>(
        p_ff, p_w2T, b2, p_h, out, BS, DD, DFF);
}